// round 4
// baseline (speedup 1.0000x reference)
#include <cuda_runtime.h>
#include <math.h>

#define KDIM 64
#define DEG 32
#define N0_MAX 65536
#define WPB 4   // warps per block

// hop-0 aggregate scratch: 65536 x 64 f32 = 16 MB (static __device__, no alloc)
__device__ float g_agg0[N0_MAX * KDIM];

// ---- cp.async helpers (16B, L1-bypass) ----
__device__ __forceinline__ void cp16(void* smem_dst, const void* gsrc) {
    unsigned d = (unsigned)__cvta_generic_to_shared(smem_dst);
    asm volatile("cp.async.cg.shared.global [%0], [%1], 16;" :: "r"(d), "l"(gsrc));
}
__device__ __forceinline__ void cp_wait_all() {
    asm volatile("cp.async.wait_all;" ::: "memory");
}

// reduce across a 16-lane half-warp (xor 8,4,2,1)
__device__ __forceinline__ float half_sum(float v) {
#pragma unroll
    for (int o = 8; o > 0; o >>= 1) v += __shfl_xor_sync(0xffffffffu, v, o);
    return v;
}

// renorm scale: min(1, 1/max(sqrt(ss), 1e-12)) == ss > 1 ? rsqrt(ss) : 1
__device__ __forceinline__ float renorm_scale(float ss) {
    return (ss > 1.0f) ? rsqrtf(ss) : 1.0f;
}

// One warp per hop-0 node. All 32 neighbor rows + target row are staged into
// smem via cp.async (deep MLP, no register pressure), then reduced:
// half-warp `sub` owns rows [16*sub, 16*sub+16); lane sl owns dims [4sl,4sl+3].
__global__ void __launch_bounds__(WPB * 32) hop0_kernel(
    const float* __restrict__ entity_emb,
    const int* __restrict__ node_ids0,
    const int* __restrict__ nbr0,
    int n0)
{
    __shared__ float4 tile[WPB][33 * 16];   // 33 rows x 256B per warp

    const int w    = threadIdx.x >> 5;
    const int node = blockIdx.x * WPB + w;
    const int lane = threadIdx.x & 31;
    const int sub  = lane >> 4;
    const int sl   = lane & 15;
    if (node >= n0) return;

    float4* my = tile[w];

    const int myidx = __ldg(nbr0 + (size_t)node * DEG + lane);
    const int tid   = __ldg(node_ids0 + node);

    // ---- stage: 16 row-chunks per lane (half-warp sub covers rows sub*16+i)
#pragma unroll
    for (int i = 0; i < 16; i++) {
        const int row = i + (sub << 4);
        const int id  = __shfl_sync(0xffffffffu, myidx, row);
        cp16(&my[row * 16 + sl], entity_emb + (size_t)id * KDIM + sl * 4);
    }
    if (sub == 0)
        cp16(&my[32 * 16 + sl], entity_emb + (size_t)tid * KDIM + sl * 4);
    cp_wait_all();
    __syncwarp();

    // ---- FM accumulate with per-row renorm ----
    float4 s = make_float4(0.f, 0.f, 0.f, 0.f);
    float4 q = make_float4(0.f, 0.f, 0.f, 0.f);
#pragma unroll
    for (int i = 0; i < 16; i++) {
        const float4 e = my[(i + (sub << 4)) * 16 + sl];
        const float ss = half_sum(e.x * e.x + e.y * e.y + e.z * e.z + e.w * e.w);
        const float sc = renorm_scale(ss);
        const float ex = e.x * sc, ey = e.y * sc, ez = e.z * sc, ew = e.w * sc;
        s.x += ex; s.y += ey; s.z += ez; s.w += ew;
        q.x += ex * ex; q.y += ey * ey; q.z += ez * ez; q.w += ew * ew;
    }

    // combine the two half-warps (same k-dims at lane ^ 16)
    s.x += __shfl_xor_sync(0xffffffffu, s.x, 16);
    s.y += __shfl_xor_sync(0xffffffffu, s.y, 16);
    s.z += __shfl_xor_sync(0xffffffffu, s.z, 16);
    s.w += __shfl_xor_sync(0xffffffffu, s.w, 16);
    q.x += __shfl_xor_sync(0xffffffffu, q.x, 16);
    q.y += __shfl_xor_sync(0xffffffffu, q.y, 16);
    q.z += __shfl_xor_sync(0xffffffffu, q.z, 16);
    q.w += __shfl_xor_sync(0xffffffffu, q.w, 16);

    const float4 t  = my[32 * 16 + sl];
    const float tsc = renorm_scale(half_sum(t.x * t.x + t.y * t.y +
                                            t.z * t.z + t.w * t.w));

    if (sub == 0) {
        float4 o;
        o.x = s.x * s.x - q.x + t.x * tsc;
        o.y = s.y * s.y - q.y + t.y * tsc;
        o.z = s.z * s.z - q.z + t.z * tsc;
        o.w = s.w * s.w - q.w + t.w * tsc;
        *((float4*)(g_agg0 + (size_t)node * KDIM) + sl) = o;
    }
}

// One warp per batch row, same cp.async staging (rows 0-31 = agg0 gathers,
// row 32 = item target, row 33 = user row).
__global__ void __launch_bounds__(WPB * 32) hop1_kernel(
    const float* __restrict__ entity_emb,
    const float* __restrict__ user_emb,
    const int* __restrict__ u,
    const int* __restrict__ item_ids,
    const int* __restrict__ nbr1_idx,
    float* __restrict__ out,
    int B)
{
    __shared__ float4 tile[WPB][34 * 16];

    const int w    = threadIdx.x >> 5;
    const int b    = blockIdx.x * WPB + w;
    const int lane = threadIdx.x & 31;
    const int sub  = lane >> 4;
    const int sl   = lane & 15;
    if (b >= B) return;

    float4* my = tile[w];

    const int myidx = __ldg(nbr1_idx + (size_t)b * DEG + lane);
    const int it    = __ldg(item_ids + b);
    const int uid   = __ldg(u + b);

#pragma unroll
    for (int i = 0; i < 16; i++) {
        const int row = i + (sub << 4);
        const int id  = __shfl_sync(0xffffffffu, myidx, row);
        cp16(&my[row * 16 + sl], g_agg0 + (size_t)id * KDIM + sl * 4);
    }
    if (sub == 0) {
        cp16(&my[32 * 16 + sl], entity_emb + (size_t)it * KDIM + sl * 4);
        cp16(&my[33 * 16 + sl], user_emb + (size_t)uid * KDIM + sl * 4);
    }
    cp_wait_all();
    __syncwarp();

    float4 s = make_float4(0.f, 0.f, 0.f, 0.f);
    float4 q = make_float4(0.f, 0.f, 0.f, 0.f);
#pragma unroll
    for (int i = 0; i < 16; i++) {
        const float4 e = my[(i + (sub << 4)) * 16 + sl];
        s.x += e.x; s.y += e.y; s.z += e.z; s.w += e.w;
        q.x += e.x * e.x; q.y += e.y * e.y;
        q.z += e.z * e.z; q.w += e.w * e.w;
    }

    s.x += __shfl_xor_sync(0xffffffffu, s.x, 16);
    s.y += __shfl_xor_sync(0xffffffffu, s.y, 16);
    s.z += __shfl_xor_sync(0xffffffffu, s.z, 16);
    s.w += __shfl_xor_sync(0xffffffffu, s.w, 16);
    q.x += __shfl_xor_sync(0xffffffffu, q.x, 16);
    q.y += __shfl_xor_sync(0xffffffffu, q.y, 16);
    q.z += __shfl_xor_sync(0xffffffffu, q.z, 16);
    q.w += __shfl_xor_sync(0xffffffffu, q.w, 16);

    const float4 t  = my[32 * 16 + sl];
    const float tsc = renorm_scale(half_sum(t.x * t.x + t.y * t.y +
                                            t.z * t.z + t.w * t.w));

    float4 items;
    items.x = s.x * s.x - q.x + t.x * tsc;
    items.y = s.y * s.y - q.y + t.y * tsc;
    items.z = s.z * s.z - q.z + t.z * tsc;
    items.w = s.w * s.w - q.w + t.w * tsc;

    const float4 usr = my[33 * 16 + sl];
    const float usc  = renorm_scale(half_sum(usr.x * usr.x + usr.y * usr.y +
                                             usr.z * usr.z + usr.w * usr.w));

    const float dot = half_sum((usr.x * items.x + usr.y * items.y +
                                usr.z * items.z + usr.w * items.w) * usc);
    if (lane == 0) out[b] = 1.0f / (1.0f + expf(-dot));
}

extern "C" void kernel_launch(void* const* d_in, const int* in_sizes, int n_in,
                              void* d_out, int out_size)
{
    const float* entity_emb = (const float*)d_in[0];
    const float* user_emb   = (const float*)d_in[1];
    // d_in[2..5] = Wa, ba, Wh, bh : dead code (softmax over singleton axis == 1)
    const int* u         = (const int*)d_in[6];
    const int* item_ids  = (const int*)d_in[7];
    const int* nbr1_idx  = (const int*)d_in[8];
    const int* node_ids0 = (const int*)d_in[9];
    const int* nbr0      = (const int*)d_in[10];

    const int B  = in_sizes[6];   // 2048
    const int n0 = in_sizes[9];   // 65536

    hop0_kernel<<<(n0 + WPB - 1) / WPB, WPB * 32>>>(entity_emb, node_ids0, nbr0, n0);
    hop1_kernel<<<(B + WPB - 1) / WPB, WPB * 32>>>(
        entity_emb, user_emb, u, item_ids, nbr1_idx, (float*)d_out, B);
}